// round 6
// baseline (speedup 1.0000x reference)
#include <cuda_runtime.h>
#include <cstdint>

// Kuramoto oscillators: B=32, N=2048, K=8, T=20.
// R6: cluster of 4 CTAs per batch (grid=128), replicated double-buffered
// phase arrays. Warp-staged producer-push: each warp, right after computing
// its 32 phases, STS's them (one contiguous 128B slice), __syncwarp, lane0
// fence.proxy.async + 3x cp.async.bulk (128B) to the peers' replicas with
// complete_tx on the peers' per-buffer mbarrier (expect = 3*2048 = 6144 B,
// 48 tx-updates per barrier per step instead of R5's 2048). Local replica is
// ordered by one __syncthreads before the wait. Fast warps' sends overlap
// slow warps' compute.
// Duplicate scatter targets: LAST k wins; n = #distinct nonzero targets.
// eps/n folded into the weights (eps=1, anneal=0).

#define Nn 2048
#define Kk 8
#define Bb 32
#define Tt 20
#define CSZ 4
#define THREADS 512
#define NPC (Nn / CSZ)                           // 512 oscillators per CTA
#define WARP_BYTES 128                           // 32 floats per warp
#define EXPECT_BYTES ((CSZ - 1) * NPC * 4)       // 6144 remote bytes / step

#define TWO_PI     6.28318530717958647692f
#define INV_TWO_PI 0.15915494309189533577f

__device__ __forceinline__ uint32_t smem_u32(const void* p) {
    uint32_t a;
    asm("{ .reg .u64 t; cvta.to.shared.u64 t, %1; cvt.u32.u64 %0, t; }"
        : "=r"(a) : "l"(p));
    return a;
}

__device__ __forceinline__ uint32_t mapa_u32(uint32_t laddr, uint32_t rank) {
    uint32_t r;
    asm("mapa.shared::cluster.u32 %0, %1, %2;" : "=r"(r) : "r"(laddr), "r"(rank));
    return r;
}

__device__ __forceinline__ void mbar_init(uint32_t laddr, uint32_t count) {
    asm volatile("mbarrier.init.shared.b64 [%0], %1;" :: "r"(laddr), "r"(count) : "memory");
}

__device__ __forceinline__ void mbar_arrive_expect_tx(uint32_t laddr, uint32_t tx) {
    asm volatile("mbarrier.arrive.expect_tx.shared.b64 _, [%0], %1;"
                 :: "r"(laddr), "r"(tx) : "memory");
}

__device__ __forceinline__ void bulk_s2s_cluster(uint32_t dst_cluster,
                                                 uint32_t src_cta,
                                                 uint32_t bytes,
                                                 uint32_t rmbar_cluster) {
    asm volatile(
        "cp.async.bulk.shared::cluster.shared::cta.mbarrier::complete_tx::bytes "
        "[%0], [%1], %2, [%3];"
        :: "r"(dst_cluster), "r"(src_cta), "r"(bytes), "r"(rmbar_cluster)
        : "memory");
}

__device__ __forceinline__ void mbar_wait(uint32_t laddr, uint32_t parity) {
    uint32_t done;
    asm volatile(
        "{ .reg .pred p;\n"
        "  mbarrier.try_wait.parity.acquire.cluster.shared::cta.b64 p, [%1], %2;\n"
        "  selp.b32 %0, 1, 0, p; }"
        : "=r"(done) : "r"(laddr), "r"(parity) : "memory");
    if (!done) {
        asm volatile(
            "{ .reg .pred p;\n"
            "WL_%=:\n"
            "  mbarrier.try_wait.parity.acquire.cluster.shared::cta.b64 p, [%0], %1, 0x989680;\n"
            "  @p bra.uni WD_%=;\n"
            "  bra.uni WL_%=;\n"
            "WD_%=: }"
            :: "r"(laddr), "r"(parity) : "memory");
    }
}

__global__ void __launch_bounds__(THREADS, 1) __cluster_dims__(CSZ, 1, 1)
osc_kernel(const float* __restrict__ coupling,   // [B,N,K]
           const float* __restrict__ phase0,     // [B,N]
           const float* __restrict__ omega,      // [B,N]
           const int*   __restrict__ conn,       // [N,K]
           float*       __restrict__ out)        // [T+1,B,N]
{
    __shared__ __align__(16) float th[2][Nn];             // replicated phases
    __shared__ __align__(8)  unsigned long long mbar[2];  // one per buffer

    uint32_t rank;
    asm("mov.u32 %0, %%cluster_ctarank;" : "=r"(rank));
    const int b    = blockIdx.x / CSZ;
    const int tid  = threadIdx.x;
    const int lane = tid & 31;
    const int n    = (int)rank * NPC + tid;

    const uint32_t mb_l0 = smem_u32(&mbar[0]);
    const uint32_t mb_l1 = smem_u32(&mbar[1]);
    if (tid == 0) {
        mbar_init(mb_l0, 1);   // 1 arrival (arming thread) + tx bytes
        mbar_init(mb_l1, 1);
    }

    // ---- prologue: dedup couplings, fold eps/n into weights ----
    float w[Kk];
    int   off[Kk];
    int idx[Kk];
    #pragma unroll
    for (int k = 0; k < Kk; ++k) idx[k] = conn[n * Kk + k];

    int cnt = 0;
    #pragma unroll
    for (int k = 0; k < Kk; ++k) {
        bool win = true;
        #pragma unroll
        for (int k2 = k + 1; k2 < Kk; ++k2) win = win && (idx[k2] != idx[k]);
        const float c = coupling[((size_t)b * Nn + n) * Kk + k];
        w[k]   = win ? c : 0.0f;
        off[k] = idx[k];
        cnt += (win && (c != 0.0f)) ? 1 : 0;
    }
    const float inv = (cnt > 0) ? (1.0f / (float)cnt) : 0.0f;
    #pragma unroll
    for (int k = 0; k < Kk; ++k) w[k] *= inv;

    float p  = phase0[(size_t)b * Nn + n];
    const float om = omega[(size_t)b * Nn + n];
    out[(size_t)b * Nn + n] = p;                 // t=0 slice

    // each CTA fills its FULL th[0] locally from gmem
    #pragma unroll
    for (int j = 0; j < CSZ; ++j) {
        const int m  = tid + j * THREADS;
        const float q = phase0[(size_t)b * Nn + m];
        th[0][m] = q - TWO_PI * rintf(q * INV_TWO_PI);
    }
    float pr = p - TWO_PI * rintf(p * INV_TWO_PI);

    // hoisted warp-slice addresses: this warp's 128B slice in both buffers,
    // the 3 peers' matching destinations, and the peers' per-buffer mbarriers.
    const int wbase = (int)rank * NPC + (tid & ~31);
    const uint32_t src_l[2] = { smem_u32(&th[0][wbase]), smem_u32(&th[1][wbase]) };
    uint32_t dst_r[2][CSZ - 1], mbr_r[2][CSZ - 1];
    {
        int q = 0;
        #pragma unroll
        for (int r = 0; r < CSZ; ++r) {
            if ((uint32_t)r != rank) {
                dst_r[0][q] = mapa_u32(src_l[0], (uint32_t)r);
                dst_r[1][q] = mapa_u32(src_l[1], (uint32_t)r);
                mbr_r[0][q] = mapa_u32(mb_l0, (uint32_t)r);
                mbr_r[1][q] = mapa_u32(mb_l1, (uint32_t)r);
                ++q;
            }
        }
    }

    __syncthreads();   // th[0] + mbarrier init complete at CTA scope
    // cluster-wide: all mbarriers initialized before any peer bulk signals
    asm volatile("barrier.cluster.arrive.aligned;" ::: "memory");
    asm volatile("barrier.cluster.wait.aligned;"   ::: "memory");

    uint32_t par[2] = {0, 0};

    // ---- time stepping ----
    #pragma unroll 1
    for (int t = 0; t < Tt; ++t) {
        const int c  = t & 1;
        const int nb = c ^ 1;

        if (t > 0) {                 // all 6144 remote bytes of buffer c in
            mbar_wait(c ? mb_l1 : mb_l0, par[c]);
            par[c] ^= 1u;
        }

        const float* __restrict__ cur = th[c];

        float acc = 0.0f;
        #pragma unroll
        for (int k = 0; k < Kk; ++k)
            acc += w[k] * __sinf(cur[off[k]] - pr);   // arg in [-2pi, 2pi]

        p += acc + om;
        const float prn = p - TWO_PI * rintf(p * INV_TWO_PI);
        pr = prn;

        // local replica slice
        th[nb][n] = prn;

        if (t < Tt - 1) {
            // warp-staged push: as soon as THIS warp's 32 phases are in smem,
            // lane0 ships the 128B slice to all 3 peers.
            __syncwarp();
            if (lane == 0) {
                asm volatile("fence.proxy.async.shared::cta;" ::: "memory");
                #pragma unroll
                for (int q = 0; q < CSZ - 1; ++q)
                    bulk_s2s_cluster(dst_r[nb][q], src_l[nb],
                                     WARP_BYTES, mbr_r[nb][q]);
            }
        }

        // global output (overlaps the in-flight bulks)
        out[(size_t)(t + 1) * (Bb * Nn) + (size_t)b * Nn + n] = p;

        if (t < Tt - 1) {
            __syncthreads();         // orders local STS for next step's reads
            if (tid == 0)
                mbar_arrive_expect_tx(nb ? mb_l1 : mb_l0, EXPECT_BYTES);
        }
    }
}

extern "C" void kernel_launch(void* const* d_in, const int* in_sizes, int n_in,
                              void* d_out, int out_size)
{
    const float* coupling = (const float*)d_in[0];   // [B,N,K] f32
    const float* phase0   = (const float*)d_in[1];   // [B,N]   f32
    const float* omega    = (const float*)d_in[2];   // [B,N]   f32
    const int*   conn     = (const int*)  d_in[3];   // [N,K]   i32
    float*       out      = (float*)d_out;           // [T+1,B,N] f32

    osc_kernel<<<Bb * CSZ, THREADS>>>(coupling, phase0, omega, conn, out);
}

// round 7
// speedup vs baseline: 1.0012x; 1.0012x over previous
#include <cuda_runtime.h>
#include <cstdint>

// Kuramoto oscillators: B=32, N=2048, K=8, T=20.
// R7: cluster of 2 CTAs per batch (grid=64), 1024 threads/CTA, 1 osc/thread.
// Replicated double-buffered phase arrays. Per step: gather 8 neighbors
// (local LDS), 8x __sinf, update, STS own 1024-slice, __syncthreads, thread0
// fence + ONE 4KB cp.async.bulk to the single peer (complete_tx on peer's
// per-buffer mbarrier, expect = 4096 B, one tx-update/step). Arming happens
// right after the wait (off the tail). Rationale: cluster tail = max-of-2
// skew instead of max-of-4, and one engine op per step.
// Duplicate scatter targets: LAST k wins; n = #distinct nonzero targets.
// eps/n folded into the weights (eps=1, anneal=0).

#define Nn 2048
#define Kk 8
#define Bb 32
#define Tt 20
#define CSZ 2
#define THREADS 1024
#define NPC (Nn / CSZ)                 // 1024 oscillators per CTA
#define SLICE_BYTES (NPC * 4)          // 4096 bytes
#define EXPECT_BYTES SLICE_BYTES       // one peer

#define TWO_PI     6.28318530717958647692f
#define INV_TWO_PI 0.15915494309189533577f

__device__ __forceinline__ uint32_t smem_u32(const void* p) {
    uint32_t a;
    asm("{ .reg .u64 t; cvta.to.shared.u64 t, %1; cvt.u32.u64 %0, t; }"
        : "=r"(a) : "l"(p));
    return a;
}

__device__ __forceinline__ uint32_t mapa_u32(uint32_t laddr, uint32_t rank) {
    uint32_t r;
    asm("mapa.shared::cluster.u32 %0, %1, %2;" : "=r"(r) : "r"(laddr), "r"(rank));
    return r;
}

__device__ __forceinline__ void mbar_init(uint32_t laddr, uint32_t count) {
    asm volatile("mbarrier.init.shared.b64 [%0], %1;" :: "r"(laddr), "r"(count) : "memory");
}

__device__ __forceinline__ void mbar_arrive_expect_tx(uint32_t laddr, uint32_t tx) {
    asm volatile("mbarrier.arrive.expect_tx.shared.b64 _, [%0], %1;"
                 :: "r"(laddr), "r"(tx) : "memory");
}

__device__ __forceinline__ void bulk_s2s_cluster(uint32_t dst_cluster,
                                                 uint32_t src_cta,
                                                 uint32_t bytes,
                                                 uint32_t rmbar_cluster) {
    asm volatile(
        "cp.async.bulk.shared::cluster.shared::cta.mbarrier::complete_tx::bytes "
        "[%0], [%1], %2, [%3];"
        :: "r"(dst_cluster), "r"(src_cta), "r"(bytes), "r"(rmbar_cluster)
        : "memory");
}

__device__ __forceinline__ void mbar_wait(uint32_t laddr, uint32_t parity) {
    uint32_t done;
    asm volatile(
        "{ .reg .pred p;\n"
        "  mbarrier.try_wait.parity.acquire.cluster.shared::cta.b64 p, [%1], %2;\n"
        "  selp.b32 %0, 1, 0, p; }"
        : "=r"(done) : "r"(laddr), "r"(parity) : "memory");
    if (!done) {
        asm volatile(
            "{ .reg .pred p;\n"
            "WL_%=:\n"
            "  mbarrier.try_wait.parity.acquire.cluster.shared::cta.b64 p, [%0], %1, 0x989680;\n"
            "  @p bra.uni WD_%=;\n"
            "  bra.uni WL_%=;\n"
            "WD_%=: }"
            :: "r"(laddr), "r"(parity) : "memory");
    }
}

__global__ void __launch_bounds__(THREADS, 1) __cluster_dims__(CSZ, 1, 1)
osc_kernel(const float* __restrict__ coupling,   // [B,N,K]
           const float* __restrict__ phase0,     // [B,N]
           const float* __restrict__ omega,      // [B,N]
           const int*   __restrict__ conn,       // [N,K]
           float*       __restrict__ out)        // [T+1,B,N]
{
    __shared__ __align__(16) float th[2][Nn];             // replicated phases
    __shared__ __align__(8)  unsigned long long mbar[2];  // one per buffer

    uint32_t rank;
    asm("mov.u32 %0, %%cluster_ctarank;" : "=r"(rank));
    const int b   = blockIdx.x / CSZ;
    const int tid = threadIdx.x;
    const int n   = (int)rank * NPC + tid;

    const uint32_t mb_l0 = smem_u32(&mbar[0]);
    const uint32_t mb_l1 = smem_u32(&mbar[1]);
    if (tid == 0) {
        mbar_init(mb_l0, 1);   // 1 arrival (arming thread) + tx bytes
        mbar_init(mb_l1, 1);
    }

    // ---- prologue: dedup couplings, fold eps/n into weights ----
    float w[Kk];
    int   off[Kk];
    int idx[Kk];
    #pragma unroll
    for (int k = 0; k < Kk; ++k) idx[k] = conn[n * Kk + k];

    int cnt = 0;
    #pragma unroll
    for (int k = 0; k < Kk; ++k) {
        bool win = true;
        #pragma unroll
        for (int k2 = k + 1; k2 < Kk; ++k2) win = win && (idx[k2] != idx[k]);
        const float c = coupling[((size_t)b * Nn + n) * Kk + k];
        w[k]   = win ? c : 0.0f;
        off[k] = idx[k];
        cnt += (win && (c != 0.0f)) ? 1 : 0;
    }
    const float inv = (cnt > 0) ? (1.0f / (float)cnt) : 0.0f;
    #pragma unroll
    for (int k = 0; k < Kk; ++k) w[k] *= inv;

    float p  = phase0[(size_t)b * Nn + n];
    const float om = omega[(size_t)b * Nn + n];
    out[(size_t)b * Nn + n] = p;                 // t=0 slice

    // each CTA fills its FULL th[0] locally from gmem (2 per thread)
    #pragma unroll
    for (int j = 0; j < CSZ; ++j) {
        const int m  = tid + j * THREADS;
        const float q = phase0[(size_t)b * Nn + m];
        th[0][m] = q - TWO_PI * rintf(q * INV_TWO_PI);
    }
    float pr = p - TWO_PI * rintf(p * INV_TWO_PI);

    // hoisted addresses: own slice in both buffers, peer's matching dst,
    // peer's per-buffer mbarriers.
    const uint32_t peer = rank ^ 1u;
    const uint32_t src_l[2] = { smem_u32(&th[0][rank * NPC]),
                                smem_u32(&th[1][rank * NPC]) };
    uint32_t dst_r[2], mbr_r[2];
    if (tid == 0) {
        dst_r[0] = mapa_u32(src_l[0], peer);
        dst_r[1] = mapa_u32(src_l[1], peer);
        mbr_r[0] = mapa_u32(mb_l0, peer);
        mbr_r[1] = mapa_u32(mb_l1, peer);
    }

    __syncthreads();   // th[0] + mbarrier init complete at CTA scope
    // cluster-wide: both mbarriers initialized before any peer bulk signals
    asm volatile("barrier.cluster.arrive.aligned;" ::: "memory");
    asm volatile("barrier.cluster.wait.aligned;"   ::: "memory");

    uint32_t par[2] = {0, 0};

    // ---- time stepping ----
    #pragma unroll 1
    for (int t = 0; t < Tt; ++t) {
        const int c  = t & 1;
        const int nb = c ^ 1;

        if (t > 0) {                 // peer's 4KB of buffer c arrived
            mbar_wait(c ? mb_l1 : mb_l0, par[c]);
            par[c] ^= 1u;
        }
        // arm next buffer's barrier early (off the tail; negative tx is legal)
        if (t < Tt - 1 && tid == 0)
            mbar_arrive_expect_tx(nb ? mb_l1 : mb_l0, EXPECT_BYTES);

        const float* __restrict__ cur = th[c];

        float acc = 0.0f;
        #pragma unroll
        for (int k = 0; k < Kk; ++k)
            acc += w[k] * __sinf(cur[off[k]] - pr);   // arg in [-2pi, 2pi]

        p += acc + om;
        const float prn = p - TWO_PI * rintf(p * INV_TWO_PI);
        pr = prn;

        // own slice into own next buffer + global output
        th[nb][n] = prn;
        out[(size_t)(t + 1) * (Bb * Nn) + (size_t)b * Nn + n] = p;

        if (t < Tt - 1) {
            __syncthreads();         // slice complete before engine reads it
            if (tid == 0) {
                asm volatile("fence.proxy.async.shared::cta;" ::: "memory");
                bulk_s2s_cluster(dst_r[nb], src_l[nb], SLICE_BYTES, mbr_r[nb]);
            }
        }
    }
}

extern "C" void kernel_launch(void* const* d_in, const int* in_sizes, int n_in,
                              void* d_out, int out_size)
{
    const float* coupling = (const float*)d_in[0];   // [B,N,K] f32
    const float* phase0   = (const float*)d_in[1];   // [B,N]   f32
    const float* omega    = (const float*)d_in[2];   // [B,N]   f32
    const int*   conn     = (const int*)  d_in[3];   // [N,K]   i32
    float*       out      = (float*)d_out;           // [T+1,B,N] f32

    osc_kernel<<<Bb * CSZ, THREADS>>>(coupling, phase0, omega, conn, out);
}